// round 8
// baseline (speedup 1.0000x reference)
#include <cuda_runtime.h>
#include <cuda_bf16.h>
#include <cstdint>

// ============================================================================
// R2Ntab: out[b] = sum_r [ x[b,:]·rw[r,:] > thr[r] ] * orw[r] + b_or[0]
//   rw[r,j]  = (w_cancel[j] >= 0) ? w_and[r,j] : 0           (bf16)
//   thr[r]   = orw[r] ? 0.999999 - b_and[r] + sum relu(rw)   else +INF
// GEMM [131072 x 256] x [256 x 128] via mma.sync m16n8k16 bf16 (plain sm_103
// target: tcgen05 unavailable), threshold-count epilogue fused in registers.
// ============================================================================

#define FEAT   256
#define RULES  128
#define WPAD   264            // padded bf16 row length -> 528B stride, no LDS conflicts
#define W_BYTES (RULES * WPAD * 2)   // 67584

// Masked bf16 weight image (padded layout) + per-rule thresholds (orw folded in).
__device__ uint4 g_w_pad4[W_BYTES / 16];
__device__ float g_thr[RULES];

// ---------------------------------------------------------------------------
// Prep: one warp per rule.
// ---------------------------------------------------------------------------
__global__ void r2n_prep(const float* __restrict__ w_cancel,
                         const float* __restrict__ w_and,
                         const float* __restrict__ b_and,
                         const float* __restrict__ w_or) {
    int wid = threadIdx.x >> 5, lid = threadIdx.x & 31;
    int r = blockIdx.x * 4 + wid;
    __nv_bfloat16* img = reinterpret_cast<__nv_bfloat16*>(g_w_pad4);

    float relu_sum = 0.0f;
    #pragma unroll
    for (int jj = 0; jj < FEAT / 32; jj++) {
        int j = lid + jj * 32;
        float wv = (w_cancel[j] >= 0.0f) ? w_and[r * FEAT + j] : 0.0f;
        relu_sum += fmaxf(wv, 0.0f);
        img[r * WPAD + j] = __float2bfloat16(wv);
    }
    #pragma unroll
    for (int d = 16; d > 0; d >>= 1)
        relu_sum += __shfl_xor_sync(0xFFFFFFFFu, relu_sum, d);
    if (lid == 0) {
        // Fold OR-weight mask into the threshold: disabled rules never fire.
        g_thr[r] = (w_or[r] > 0.0f)
                 ? (0.999999f - b_and[r] + relu_sum)
                 : __int_as_float(0x7f800000);   // +INF
    }
}

// ---------------------------------------------------------------------------
// mma.sync m16n8k16 row.col f32.bf16.bf16.f32 (sm_80+, works on plain sm_103)
// ---------------------------------------------------------------------------
__device__ __forceinline__ void mma_bf16(float* d, const uint32_t* a,
                                         uint32_t b0, uint32_t b1) {
    asm volatile(
        "mma.sync.aligned.m16n8k16.row.col.f32.bf16.bf16.f32 "
        "{%0,%1,%2,%3}, {%4,%5,%6,%7}, {%8,%9}, {%0,%1,%2,%3};"
        : "+f"(d[0]), "+f"(d[1]), "+f"(d[2]), "+f"(d[3])
        : "r"(a[0]), "r"(a[1]), "r"(a[2]), "r"(a[3]), "r"(b0), "r"(b1));
}

__device__ __forceinline__ uint32_t f2_to_bf2(float2 v) {
    __nv_bfloat162 h = __float22bfloat162_rn(v);   // .x = v.x (low half)
    return *reinterpret_cast<uint32_t*>(&h);
}

// ---------------------------------------------------------------------------
// Main: 256 threads = 8 warps; each warp owns 32 batch rows (two m16 A-tiles
// sharing every B fragment -> halves LDS traffic). A loaded gmem->reg in the
// native fragment pattern (no smem staging). W + thr staged in smem once.
// SMEM: [0,512) thr, [512, 512+67584) W (padded rows).
// ---------------------------------------------------------------------------
#define SMEM_TOTAL (512 + W_BYTES)

__global__ void __launch_bounds__(256)
r2n_main(const float* __restrict__ x,
         const float* __restrict__ b_or,
         float* __restrict__ out,
         int nrows) {
    extern __shared__ char smem[];
    float* sThr = reinterpret_cast<float*>(smem);
    __nv_bfloat16* sW = reinterpret_cast<__nv_bfloat16*>(smem + 512);
    int tid = threadIdx.x;

    // Stage weight image + thresholds.
    {
        uint4* d4 = reinterpret_cast<uint4*>(smem + 512);
        #pragma unroll
        for (int i = 0; i < (W_BYTES / 16 + 255) / 256; i++) {
            int k = tid + i * 256;
            if (k < W_BYTES / 16) d4[k] = g_w_pad4[k];
        }
        if (tid < RULES) sThr[tid] = g_thr[tid];
    }
    __syncthreads();

    const int lane = tid & 31, warp = tid >> 5;
    const int g = lane >> 2, q = lane & 3;     // groupID, quad-lane
    const int rowbase = blockIdx.x * 256 + warp * 32;

    // This thread's 4 fragment rows: rowbase + g + {0,8,16,24} (clamped).
    const float* p[4];
    #pragma unroll
    for (int t = 0; t < 4; t++) {
        int r = rowbase + g + t * 8;
        int rc = (r < nrows) ? r : 0;
        p[t] = x + (size_t)rc * FEAT + q * 2;
    }

    float acc[2][16][4];
    #pragma unroll
    for (int t = 0; t < 2; t++)
        #pragma unroll
        for (int nt = 0; nt < 16; nt++)
            #pragma unroll
            for (int i = 0; i < 4; i++) acc[t][nt][i] = 0.0f;

    // Mainloop: 16 K-steps of k=16.
    #pragma unroll 4
    for (int ks = 0; ks < 16; ks++) {
        const int c0 = ks * 16;
        uint32_t A[2][4];
        #pragma unroll
        for (int t = 0; t < 4; t++) {
            float2 v0 = *reinterpret_cast<const float2*>(p[t] + c0);      // k c0,c0+1
            float2 v1 = *reinterpret_cast<const float2*>(p[t] + c0 + 8);  // k c0+8,+9
            A[t >> 1][t & 1]       = f2_to_bf2(v0);   // a0 / a1
            A[t >> 1][2 + (t & 1)] = f2_to_bf2(v1);   // a2 / a3
        }
        #pragma unroll
        for (int nt = 0; nt < 16; nt++) {
            const uint32_t* bp = reinterpret_cast<const uint32_t*>(
                sW + (nt * 8 + g) * WPAD + c0 + q * 2);
            uint32_t b0 = bp[0];   // k = c0+q*2, +1
            uint32_t b1 = bp[4];   // k = c0+q*2+8, +9
            mma_bf16(acc[0][nt], A[0], b0, b1);
            mma_bf16(acc[1][nt], A[1], b0, b1);
        }
    }

    // Epilogue: threshold-count, quad reduce, coalesced store.
    const float bor = __ldg(b_or);
    #pragma unroll
    for (int t = 0; t < 2; t++) {              // A-tile: rows g+16t, g+16t+8
        float c0s = 0.0f, c1s = 0.0f;
        #pragma unroll
        for (int nt = 0; nt < 16; nt++) {
            float t0 = sThr[nt * 8 + q * 2];
            float t1 = sThr[nt * 8 + q * 2 + 1];
            c0s += (acc[t][nt][0] > t0) ? 1.0f : 0.0f;
            c0s += (acc[t][nt][1] > t1) ? 1.0f : 0.0f;
            c1s += (acc[t][nt][2] > t0) ? 1.0f : 0.0f;
            c1s += (acc[t][nt][3] > t1) ? 1.0f : 0.0f;
        }
        c0s += __shfl_xor_sync(0xFFFFFFFFu, c0s, 1);
        c0s += __shfl_xor_sync(0xFFFFFFFFu, c0s, 2);
        c1s += __shfl_xor_sync(0xFFFFFFFFu, c1s, 1);
        c1s += __shfl_xor_sync(0xFFFFFFFFu, c1s, 2);
        if (q == 0) {
            int r0 = rowbase + g + t * 16;
            int r1 = r0 + 8;
            if (r0 < nrows) out[r0] = c0s + bor;
            if (r1 < nrows) out[r1] = c1s + bor;
        }
    }
}

// ---------------------------------------------------------------------------
// kernel_launch
// ---------------------------------------------------------------------------
extern "C" void kernel_launch(void* const* d_in, const int* in_sizes, int n_in,
                              void* d_out, int out_size) {
    const float* x        = (const float*)d_in[0];
    const float* w_cancel = (const float*)d_in[1];
    const float* w_and    = (const float*)d_in[2];
    const float* b_and    = (const float*)d_in[3];
    const float* w_or     = (const float*)d_in[4];
    const float* b_or     = (const float*)d_in[5];
    float* out = (float*)d_out;

    int nrows = in_sizes[0] / FEAT;
    int nblocks = (nrows + 255) / 256;

    r2n_prep<<<RULES / 4, 128>>>(w_cancel, w_and, b_and, w_or);

    cudaFuncSetAttribute(r2n_main,
                         cudaFuncAttributeMaxDynamicSharedMemorySize, SMEM_TOTAL);
    r2n_main<<<nblocks, 256, SMEM_TOTAL>>>(x, b_or, out, nrows);

    (void)n_in; (void)out_size;
}

// round 10
// speedup vs baseline: 1.0412x; 1.0412x over previous
#include <cuda_runtime.h>
#include <cuda_bf16.h>
#include <cstdint>

// ============================================================================
// R2Ntab: out[b] = sum_r [ x[b,:]·rw[r,:] > thr[r] ] * orw[r] + b_or[0]
//   rw[r,j]  = (w_cancel[j] >= 0) ? w_and[r,j] : 0           (bf16)
//   thr[r]   = orw[r] ? 0.999999 - b_and[r] + sum relu(rw)   else +INF
// GEMM [131072 x 256] x [256 x 128] via mma.sync m16n8k16 bf16 (plain sm_103
// target). R10 == R9 resubmit (R9 bench was an infra failure): 128-thread CTAs
// with 3 CTAs/SM residency + software-pipelined (double-buffered) A-fragment
// loads to fix the occupancy/MLP bound seen in R8 (occ 12.1%, DRAM 30.7%).
// ============================================================================

#define FEAT   256
#define RULES  128
#define WPAD   264            // padded bf16 row -> 528B stride: banks 4g+q, conflict-free
#define W_BYTES (RULES * WPAD * 2)   // 67584

__device__ uint4 g_w_pad4[W_BYTES / 16];
__device__ float g_thr[RULES];

// ---------------------------------------------------------------------------
// Prep: one warp per rule. Mask by w_cancel sign, fold orw into threshold.
// ---------------------------------------------------------------------------
__global__ void r2n_prep(const float* __restrict__ w_cancel,
                         const float* __restrict__ w_and,
                         const float* __restrict__ b_and,
                         const float* __restrict__ w_or) {
    int wid = threadIdx.x >> 5, lid = threadIdx.x & 31;
    int r = blockIdx.x * 4 + wid;
    __nv_bfloat16* img = reinterpret_cast<__nv_bfloat16*>(g_w_pad4);

    float relu_sum = 0.0f;
    #pragma unroll
    for (int jj = 0; jj < FEAT / 32; jj++) {
        int j = lid + jj * 32;
        float wv = (w_cancel[j] >= 0.0f) ? w_and[r * FEAT + j] : 0.0f;
        relu_sum += fmaxf(wv, 0.0f);
        img[r * WPAD + j] = __float2bfloat16(wv);
    }
    #pragma unroll
    for (int d = 16; d > 0; d >>= 1)
        relu_sum += __shfl_xor_sync(0xFFFFFFFFu, relu_sum, d);
    if (lid == 0) {
        g_thr[r] = (w_or[r] > 0.0f)
                 ? (0.999999f - b_and[r] + relu_sum)
                 : __int_as_float(0x7f800000);   // +INF: rule never fires
    }
}

// ---------------------------------------------------------------------------
// mma.sync m16n8k16 row.col f32.bf16.bf16.f32
// ---------------------------------------------------------------------------
__device__ __forceinline__ void mma_bf16(float* d, const uint32_t* a,
                                         uint32_t b0, uint32_t b1) {
    asm volatile(
        "mma.sync.aligned.m16n8k16.row.col.f32.bf16.bf16.f32 "
        "{%0,%1,%2,%3}, {%4,%5,%6,%7}, {%8,%9}, {%0,%1,%2,%3};"
        : "+f"(d[0]), "+f"(d[1]), "+f"(d[2]), "+f"(d[3])
        : "r"(a[0]), "r"(a[1]), "r"(a[2]), "r"(a[3]), "r"(b0), "r"(b1));
}

__device__ __forceinline__ uint32_t f2_to_bf2(float2 v) {
    __nv_bfloat162 h = __float22bfloat162_rn(v);
    return *reinterpret_cast<uint32_t*>(&h);
}

// ---------------------------------------------------------------------------
// Main: 128 threads = 4 warps; each warp owns 32 batch rows (two m16 A-tiles
// per B fragment -> halves LDS traffic). A loaded gmem->reg in the native
// fragment pattern, double-buffered one K-step ahead. W + thr staged in smem
// once per CTA (L2-resident after wave 1).
// SMEM: [0,512) thr, [512, 512+W_BYTES) W.
// ---------------------------------------------------------------------------
#define SMEM_TOTAL (512 + W_BYTES)

__global__ void __launch_bounds__(128, 3)
r2n_main(const float* __restrict__ x,
         const float* __restrict__ b_or,
         float* __restrict__ out,
         int nrows) {
    extern __shared__ char smem[];
    float* sThr = reinterpret_cast<float*>(smem);
    __nv_bfloat16* sW = reinterpret_cast<__nv_bfloat16*>(smem + 512);
    int tid = threadIdx.x;

    // Stage weight image + thresholds (4224 uint4, 128 threads -> 33 iters).
    {
        uint4* d4 = reinterpret_cast<uint4*>(smem + 512);
        #pragma unroll
        for (int i = 0; i < (W_BYTES / 16 + 127) / 128; i++) {
            int k = tid + i * 128;
            if (k < W_BYTES / 16) d4[k] = g_w_pad4[k];
        }
        if (tid < RULES) sThr[tid] = g_thr[tid];
    }
    __syncthreads();

    const int lane = tid & 31, warp = tid >> 5;
    const int g = lane >> 2, q = lane & 3;     // groupID, quad-lane
    const int rowbase = blockIdx.x * 128 + warp * 32;

    // Fragment-row base pointers: rows rowbase + g + {0,8,16,24} (clamped).
    const float* p[4];
    #pragma unroll
    for (int t = 0; t < 4; t++) {
        int r = rowbase + g + t * 8;
        int rc = (r < nrows) ? r : 0;
        p[t] = x + (size_t)rc * FEAT + q * 2;
    }

    float acc[2][16][4];
    #pragma unroll
    for (int t = 0; t < 2; t++)
        #pragma unroll
        for (int nt = 0; nt < 16; nt++)
            #pragma unroll
            for (int i = 0; i < 4; i++) acc[t][nt][i] = 0.0f;

    // Double-buffered A fragments: Abuf[b][tile*4 + j].
    uint32_t Abuf[2][8];

    #define LOAD_A(dst, ksv)                                                   \
        do {                                                                   \
            const int _c0 = (ksv) * 16;                                        \
            _Pragma("unroll")                                                  \
            for (int t = 0; t < 4; t++) {                                      \
                float2 v0 = *reinterpret_cast<const float2*>(p[t] + _c0);      \
                float2 v1 = *reinterpret_cast<const float2*>(p[t] + _c0 + 8);  \
                (dst)[(t >> 1) * 4 + (t & 1)]     = f2_to_bf2(v0);             \
                (dst)[(t >> 1) * 4 + 2 + (t & 1)] = f2_to_bf2(v1);             \
            }                                                                  \
        } while (0)

    LOAD_A(Abuf[0], 0);

    // Mainloop: 16 K-steps of k=16, fully unrolled, prefetch ks+1 before MMAs.
    #pragma unroll
    for (int ks = 0; ks < 16; ks++) {
        const uint32_t* Ac = Abuf[ks & 1];
        if (ks < 15) LOAD_A(Abuf[(ks + 1) & 1], ks + 1);
        const int c0 = ks * 16;
        #pragma unroll
        for (int nt = 0; nt < 16; nt++) {
            const uint32_t* bp = reinterpret_cast<const uint32_t*>(
                sW + (nt * 8 + g) * WPAD + c0 + q * 2);
            uint32_t b0 = bp[0];   // k = c0+q*2, +1
            uint32_t b1 = bp[4];   // k = c0+q*2+8, +9
            mma_bf16(acc[0][nt], Ac + 0, b0, b1);
            mma_bf16(acc[1][nt], Ac + 4, b0, b1);
        }
    }
    #undef LOAD_A

    // Epilogue: threshold-count, quad reduce, coalesced store.
    const float bor = __ldg(b_or);
    #pragma unroll
    for (int t = 0; t < 2; t++) {              // A-tile rows: g+16t, g+16t+8
        float c0s = 0.0f, c1s = 0.0f;
        #pragma unroll
        for (int nt = 0; nt < 16; nt++) {
            float t0 = sThr[nt * 8 + q * 2];
            float t1 = sThr[nt * 8 + q * 2 + 1];
            c0s += (acc[t][nt][0] > t0) ? 1.0f : 0.0f;
            c0s += (acc[t][nt][1] > t1) ? 1.0f : 0.0f;
            c1s += (acc[t][nt][2] > t0) ? 1.0f : 0.0f;
            c1s += (acc[t][nt][3] > t1) ? 1.0f : 0.0f;
        }
        c0s += __shfl_xor_sync(0xFFFFFFFFu, c0s, 1);
        c0s += __shfl_xor_sync(0xFFFFFFFFu, c0s, 2);
        c1s += __shfl_xor_sync(0xFFFFFFFFu, c1s, 1);
        c1s += __shfl_xor_sync(0xFFFFFFFFu, c1s, 2);
        if (q == 0) {
            int r0 = rowbase + g + t * 16;
            int r1 = r0 + 8;
            if (r0 < nrows) out[r0] = c0s + bor;
            if (r1 < nrows) out[r1] = c1s + bor;
        }
    }
}

// ---------------------------------------------------------------------------
// kernel_launch
// ---------------------------------------------------------------------------
extern "C" void kernel_launch(void* const* d_in, const int* in_sizes, int n_in,
                              void* d_out, int out_size) {
    const float* x        = (const float*)d_in[0];
    const float* w_cancel = (const float*)d_in[1];
    const float* w_and    = (const float*)d_in[2];
    const float* b_and    = (const float*)d_in[3];
    const float* w_or     = (const float*)d_in[4];
    const float* b_or     = (const float*)d_in[5];
    float* out = (float*)d_out;

    int nrows = in_sizes[0] / FEAT;
    int nblocks = (nrows + 127) / 128;

    r2n_prep<<<RULES / 4, 128>>>(w_cancel, w_and, b_and, w_or);

    cudaFuncSetAttribute(r2n_main,
                         cudaFuncAttributeMaxDynamicSharedMemorySize, SMEM_TOTAL);
    r2n_main<<<nblocks, 128, SMEM_TOTAL>>>(x, b_or, out, nrows);

    (void)n_in; (void)out_size;
}

// round 13
// speedup vs baseline: 1.3767x; 1.3223x over previous
#include <cuda_runtime.h>
#include <cuda_bf16.h>
#include <cstdint>

// ============================================================================
// R2Ntab: out[b] = sum_r [ x[b,:]·rw[r,:] > thr[r] ] * orw[r] + b_or[0]
//   rw[r,j]  = (w_cancel[j] >= 0) ? w_and[r,j] : 0           (bf16)
//   thr[r]   = orw[r] ? 0.999999 - b_and[r] + sum relu(rw)   else +INF
// GEMM [131072 x 256] x [256 x 128] via mma.sync m16n8k16 bf16 (plain sm_103
// target). R11: cp.async (LDGSTS) depth-4 smem ring for A decouples gmem loads
// from compute — R10 showed the reg double-buffer never hid latency because
// the cvt consumer sat adjacent to the LDG (DRAM stuck at 30.8%).
// ============================================================================

#define FEAT   256
#define RULES  128
#define WPAD   264             // W row pad -> 528B stride: B-frag banks 4g+q, conflict-free
#define W_BYTES (RULES * WPAD * 2)    // 67584

#define NSTAGE    4
#define STG_ROW   80           // 16 fp32 used, padded to 80B (16B-aligned cp.async dst)
#define STG_BYTES (128 * STG_ROW)     // 10240
#define SM_W      512
#define SM_A      (SM_W + W_BYTES)    // 68096 (16B aligned)
#define SMEM_TOTAL (SM_A + NSTAGE * STG_BYTES)   // 109056 -> 2 CTAs/SM

__device__ uint4 g_w_pad4[W_BYTES / 16];
__device__ float g_thr[RULES];

// ---------------------------------------------------------------------------
// Prep: one warp per rule. Mask by w_cancel sign, fold orw into threshold.
// ---------------------------------------------------------------------------
__global__ void r2n_prep(const float* __restrict__ w_cancel,
                         const float* __restrict__ w_and,
                         const float* __restrict__ b_and,
                         const float* __restrict__ w_or) {
    int wid = threadIdx.x >> 5, lid = threadIdx.x & 31;
    int r = blockIdx.x * 4 + wid;
    __nv_bfloat16* img = reinterpret_cast<__nv_bfloat16*>(g_w_pad4);

    float relu_sum = 0.0f;
    #pragma unroll
    for (int jj = 0; jj < FEAT / 32; jj++) {
        int j = lid + jj * 32;
        float wv = (w_cancel[j] >= 0.0f) ? w_and[r * FEAT + j] : 0.0f;
        relu_sum += fmaxf(wv, 0.0f);
        img[r * WPAD + j] = __float2bfloat16(wv);
    }
    #pragma unroll
    for (int d = 16; d > 0; d >>= 1)
        relu_sum += __shfl_xor_sync(0xFFFFFFFFu, relu_sum, d);
    if (lid == 0) {
        g_thr[r] = (w_or[r] > 0.0f)
                 ? (0.999999f - b_and[r] + relu_sum)
                 : __int_as_float(0x7f800000);   // +INF: rule never fires
    }
}

// ---------------------------------------------------------------------------
// PTX helpers
// ---------------------------------------------------------------------------
__device__ __forceinline__ void mma_bf16(float* d, const uint32_t* a,
                                         uint32_t b0, uint32_t b1) {
    asm volatile(
        "mma.sync.aligned.m16n8k16.row.col.f32.bf16.bf16.f32 "
        "{%0,%1,%2,%3}, {%4,%5,%6,%7}, {%8,%9}, {%0,%1,%2,%3};"
        : "+f"(d[0]), "+f"(d[1]), "+f"(d[2]), "+f"(d[3])
        : "r"(a[0]), "r"(a[1]), "r"(a[2]), "r"(a[3]), "r"(b0), "r"(b1));
}

__device__ __forceinline__ uint32_t f2_to_bf2(float2 v) {
    __nv_bfloat162 h = __float22bfloat162_rn(v);
    return *reinterpret_cast<uint32_t*>(&h);
}

__device__ __forceinline__ uint32_t smem_u32(const void* p) {
    uint32_t a;
    asm("{ .reg .u64 t; cvta.to.shared.u64 t, %1; cvt.u32.u64 %0, t; }"
        : "=r"(a) : "l"(p));
    return a;
}

__device__ __forceinline__ void cp_async16(uint32_t dst, const void* src) {
    asm volatile("cp.async.cg.shared.global [%0], [%1], 16;"
                 :: "r"(dst), "l"(src) : "memory");
}
__device__ __forceinline__ void cp_commit() {
    asm volatile("cp.async.commit_group;" ::: "memory");
}
// Constant-folded under full unroll.
__device__ __forceinline__ void cp_wait_dyn(int n) {
    if (n >= 2)      asm volatile("cp.async.wait_group 2;" ::: "memory");
    else if (n == 1) asm volatile("cp.async.wait_group 1;" ::: "memory");
    else             asm volatile("cp.async.wait_group 0;" ::: "memory");
}

// ---------------------------------------------------------------------------
// Main: 128 threads = 4 warps; each warp owns 32 rows x 128 rules.
// A: gmem -> smem ring (cp.async, depth 4, 1 K-step of feats per stage),
//    fragments via LDS.64 fp32 + cvt. W/thr staged once.
// ---------------------------------------------------------------------------
__global__ void __launch_bounds__(128, 2)
r2n_main(const float* __restrict__ x,
         const float* __restrict__ b_or,
         float* __restrict__ out,
         int nrows) {
    extern __shared__ char smem[];
    float* sThr = reinterpret_cast<float*>(smem);
    __nv_bfloat16* sW = reinterpret_cast<__nv_bfloat16*>(smem + SM_W);
    const uint32_t sb = smem_u32(smem);
    const int tid = threadIdx.x;

    // Per-thread cp.async geometry: 4 chunks of 16B per stage.
    // chunk i: row = (tid>>2) + 32*i, byte offset in 64B row-slab = (tid&3)*16.
    const int crow = tid >> 2;
    const int cfo  = (tid & 3) * 16;
    const char* srcb[4];
    uint32_t    dstb[4];
    #pragma unroll
    for (int i = 0; i < 4; i++) {
        int row = crow + 32 * i;
        long rg = (long)blockIdx.x * 128 + row;
        if (rg >= nrows) rg = nrows - 1;            // clamp (dup row, out guarded)
        srcb[i] = reinterpret_cast<const char*>(x + (size_t)rg * FEAT) + cfo;
        dstb[i] = sb + SM_A + (uint32_t)(row * STG_ROW + cfo);
    }

    auto issue_stage = [&](int s) {
        const uint32_t slot = (uint32_t)(s & (NSTAGE - 1)) * STG_BYTES;
        const int gofs = s * 64;                    // 16 floats per stage
        #pragma unroll
        for (int i = 0; i < 4; i++)
            cp_async16(dstb[i] + slot, srcb[i] + gofs);
    };

    // Prologue: start A stages 0..2 BEFORE W staging so DRAM fills early.
    issue_stage(0); cp_commit();
    issue_stage(1); cp_commit();
    issue_stage(2); cp_commit();

    // Stage W (4224 uint4 = 33 per thread, exact) + thresholds.
    {
        uint4* d4 = reinterpret_cast<uint4*>(smem + SM_W);
        #pragma unroll
        for (int i = 0; i < 33; i++)
            d4[tid + i * 128] = g_w_pad4[tid + i * 128];
        if (tid < RULES) sThr[tid] = g_thr[tid];
    }
    __syncthreads();

    const int lane = tid & 31, warp = tid >> 5;
    const int g = lane >> 2, q = lane & 3;          // groupID, quad-lane
    const int rowbase = blockIdx.x * 128 + warp * 32;

    float acc[2][16][4];
    #pragma unroll
    for (int t = 0; t < 2; t++)
        #pragma unroll
        for (int nt = 0; nt < 16; nt++)
            #pragma unroll
            for (int i = 0; i < 4; i++) acc[t][nt][i] = 0.0f;

    // Mainloop: 16 K-steps of k=16. Per iter: wait stage ks, barrier (also
    // licenses overwrite of slot (ks+3)&3, last read in compute(ks-1)),
    // issue stage ks+3, compute.
    #pragma unroll
    for (int ks = 0; ks < 16; ks++) {
        cp_wait_dyn(ks <= 13 ? 2 : 15 - ks);
        __syncthreads();
        if (ks < 13) { issue_stage(ks + 3); cp_commit(); }

        // A fragments: rows warp*32 + g + 8t, k = {2q,2q+1} and {2q+8,2q+9}.
        const char* sa = smem + SM_A + (ks & (NSTAGE - 1)) * STG_BYTES;
        uint32_t A[2][4];
        #pragma unroll
        for (int t = 0; t < 4; t++) {
            const char* rp = sa + (warp * 32 + g + 8 * t) * STG_ROW + q * 8;
            float2 v0 = *reinterpret_cast<const float2*>(rp);
            float2 v1 = *reinterpret_cast<const float2*>(rp + 32);
            A[t >> 1][t & 1]       = f2_to_bf2(v0);
            A[t >> 1][2 + (t & 1)] = f2_to_bf2(v1);
        }

        const int c0 = ks * 16;
        #pragma unroll
        for (int nt = 0; nt < 16; nt++) {
            const uint32_t* bp = reinterpret_cast<const uint32_t*>(
                sW + (nt * 8 + g) * WPAD + c0 + q * 2);
            uint32_t b0 = bp[0];   // k = c0+q*2, +1
            uint32_t b1 = bp[4];   // k = c0+q*2+8, +9
            mma_bf16(acc[0][nt], A[0], b0, b1);
            mma_bf16(acc[1][nt], A[1], b0, b1);
        }
    }

    // Epilogue: threshold-count, quad reduce, coalesced store.
    const float bor = __ldg(b_or);
    #pragma unroll
    for (int t = 0; t < 2; t++) {              // A-tile rows: g+16t, g+16t+8
        float c0s = 0.0f, c1s = 0.0f;
        #pragma unroll
        for (int nt = 0; nt < 16; nt++) {
            float t0 = sThr[nt * 8 + q * 2];
            float t1 = sThr[nt * 8 + q * 2 + 1];
            c0s += (acc[t][nt][0] > t0) ? 1.0f : 0.0f;
            c0s += (acc[t][nt][1] > t1) ? 1.0f : 0.0f;
            c1s += (acc[t][nt][2] > t0) ? 1.0f : 0.0f;
            c1s += (acc[t][nt][3] > t1) ? 1.0f : 0.0f;
        }
        c0s += __shfl_xor_sync(0xFFFFFFFFu, c0s, 1);
        c0s += __shfl_xor_sync(0xFFFFFFFFu, c0s, 2);
        c1s += __shfl_xor_sync(0xFFFFFFFFu, c1s, 1);
        c1s += __shfl_xor_sync(0xFFFFFFFFu, c1s, 2);
        if (q == 0) {
            int r0 = rowbase + g + t * 16;
            int r1 = r0 + 8;
            if (r0 < nrows) out[r0] = c0s + bor;
            if (r1 < nrows) out[r1] = c1s + bor;
        }
    }
}

// ---------------------------------------------------------------------------
// kernel_launch
// ---------------------------------------------------------------------------
extern "C" void kernel_launch(void* const* d_in, const int* in_sizes, int n_in,
                              void* d_out, int out_size) {
    const float* x        = (const float*)d_in[0];
    const float* w_cancel = (const float*)d_in[1];
    const float* w_and    = (const float*)d_in[2];
    const float* b_and    = (const float*)d_in[3];
    const float* w_or     = (const float*)d_in[4];
    const float* b_or     = (const float*)d_in[5];
    float* out = (float*)d_out;

    int nrows = in_sizes[0] / FEAT;
    int nblocks = (nrows + 127) / 128;

    r2n_prep<<<RULES / 4, 128>>>(w_cancel, w_and, b_and, w_or);

    cudaFuncSetAttribute(r2n_main,
                         cudaFuncAttributeMaxDynamicSharedMemorySize, SMEM_TOTAL);
    r2n_main<<<nblocks, 128, SMEM_TOTAL>>>(x, b_or, out, nrows);

    (void)n_in; (void)out_size;
}

// round 14
// speedup vs baseline: 1.5187x; 1.1031x over previous
#include <cuda_runtime.h>
#include <cuda_bf16.h>
#include <cstdint>

// ============================================================================
// R2Ntab: out[b] = sum_r [ x[b,:]·rw[r,:] > thr[r] ] * orw[r] + b_or[0]
//   rw[r,j]  = (w_cancel[j] >= 0) ? w_and[r,j] : 0           (bf16)
//   thr[r]   = orw[r] ? 0.999999 - b_and[r] + sum relu(rw)   else +INF
// GEMM [131072 x 256] x [256 x 128] via mma.sync m16n8k16 bf16 (plain sm_103
// target). R14: per-WARP private cp.async rings — no __syncthreads in the
// mainloop. R13 showed the CTA-wide barrier+wait coupled all warps into
// lockstep bursts (DRAM stuck at 45%, ~1300 cyc/K-step vs ~500 steady-state).
// ============================================================================

#define FEAT   256
#define RULES  128
#define WPAD   264             // W row pad -> 528B stride: B-frag banks 4g+q, conflict-free
#define W_BYTES (RULES * WPAD * 2)    // 67584

#define NSTAGE    4
#define STG_ROW   80           // 16 fp32 used, 16B-aligned; write 16B-groups 5*l8+lq mod 8: conflict-free
#define WSLAB     (NSTAGE * 32 * STG_ROW)   // 10240 per warp
#define SM_W      512
#define SM_A      (SM_W + W_BYTES)          // 68096 (16B aligned)
#define SMEM_TOTAL (SM_A + 4 * WSLAB)       // 109056 -> 2 CTAs/SM

__device__ uint4 g_w_pad4[W_BYTES / 16];
__device__ float g_thr[RULES];

// ---------------------------------------------------------------------------
// Prep: one warp per rule. Mask by w_cancel sign, fold orw into threshold.
// ---------------------------------------------------------------------------
__global__ void r2n_prep(const float* __restrict__ w_cancel,
                         const float* __restrict__ w_and,
                         const float* __restrict__ b_and,
                         const float* __restrict__ w_or) {
    int wid = threadIdx.x >> 5, lid = threadIdx.x & 31;
    int r = blockIdx.x * 4 + wid;
    __nv_bfloat16* img = reinterpret_cast<__nv_bfloat16*>(g_w_pad4);

    float relu_sum = 0.0f;
    #pragma unroll
    for (int jj = 0; jj < FEAT / 32; jj++) {
        int j = lid + jj * 32;
        float wv = (w_cancel[j] >= 0.0f) ? w_and[r * FEAT + j] : 0.0f;
        relu_sum += fmaxf(wv, 0.0f);
        img[r * WPAD + j] = __float2bfloat16(wv);
    }
    #pragma unroll
    for (int d = 16; d > 0; d >>= 1)
        relu_sum += __shfl_xor_sync(0xFFFFFFFFu, relu_sum, d);
    if (lid == 0) {
        g_thr[r] = (w_or[r] > 0.0f)
                 ? (0.999999f - b_and[r] + relu_sum)
                 : __int_as_float(0x7f800000);   // +INF: rule never fires
    }
}

// ---------------------------------------------------------------------------
// PTX helpers
// ---------------------------------------------------------------------------
__device__ __forceinline__ void mma_bf16(float* d, const uint32_t* a,
                                         uint32_t b0, uint32_t b1) {
    asm volatile(
        "mma.sync.aligned.m16n8k16.row.col.f32.bf16.bf16.f32 "
        "{%0,%1,%2,%3}, {%4,%5,%6,%7}, {%8,%9}, {%0,%1,%2,%3};"
        : "+f"(d[0]), "+f"(d[1]), "+f"(d[2]), "+f"(d[3])
        : "r"(a[0]), "r"(a[1]), "r"(a[2]), "r"(a[3]), "r"(b0), "r"(b1));
}

__device__ __forceinline__ uint32_t f2_to_bf2(float2 v) {
    __nv_bfloat162 h = __float22bfloat162_rn(v);
    return *reinterpret_cast<uint32_t*>(&h);
}

__device__ __forceinline__ uint32_t smem_u32(const void* p) {
    uint32_t a;
    asm("{ .reg .u64 t; cvta.to.shared.u64 t, %1; cvt.u32.u64 %0, t; }"
        : "=r"(a) : "l"(p));
    return a;
}

__device__ __forceinline__ void cp_async16(uint32_t dst, const void* src) {
    asm volatile("cp.async.cg.shared.global [%0], [%1], 16;"
                 :: "r"(dst), "l"(src) : "memory");
}
__device__ __forceinline__ void cp_commit() {
    asm volatile("cp.async.commit_group;" ::: "memory");
}
__device__ __forceinline__ void cp_wait_dyn(int n) {  // constant under unroll
    if (n >= 2)      asm volatile("cp.async.wait_group 2;" ::: "memory");
    else if (n == 1) asm volatile("cp.async.wait_group 1;" ::: "memory");
    else             asm volatile("cp.async.wait_group 0;" ::: "memory");
}

// ---------------------------------------------------------------------------
// Main: 128 threads = 4 warps; each warp owns 32 rows x 128 rules with a
// PRIVATE cp.async ring (depth 4, 1 K-step of feats per stage). Mainloop has
// no CTA barrier: wait_group + __syncwarp only. W/thr staged once.
// ---------------------------------------------------------------------------
__global__ void __launch_bounds__(128, 2)
r2n_main(const float* __restrict__ x,
         const float* __restrict__ b_or,
         float* __restrict__ out,
         int nrows) {
    extern __shared__ char smem[];
    float* sThr = reinterpret_cast<float*>(smem);
    __nv_bfloat16* sW = reinterpret_cast<__nv_bfloat16*>(smem + SM_W);
    const uint32_t sb = smem_u32(smem);
    const int tid = threadIdx.x;
    const int lane = tid & 31, warp = tid >> 5;
    const int l8 = lane >> 2, lq = lane & 3;       // cp.async: row-sub, chunk
    const int g = l8, q = lq;                      // mma: groupID, quad-lane
    const int rowbase = blockIdx.x * 128 + warp * 32;

    // cp.async geometry: lane covers rows rowbase + l8 + 8i (i=0..3), 16B
    // chunk lq. Per stage: 4 cp.async16 per lane = 2KB per warp.
    const char* srcb[4];
    uint32_t    dstb[4];
    #pragma unroll
    for (int i = 0; i < 4; i++) {
        int row = l8 + 8 * i;
        long rg = (long)rowbase + row;
        if (rg >= nrows) rg = nrows - 1;           // clamp (dup row, out guarded)
        srcb[i] = reinterpret_cast<const char*>(x + (size_t)rg * FEAT) + lq * 16;
        dstb[i] = sb + SM_A + (uint32_t)(warp * WSLAB + row * STG_ROW + lq * 16);
    }

    auto issue_stage = [&](int s) {
        const uint32_t slot = (uint32_t)(s & (NSTAGE - 1)) * (32 * STG_ROW);
        const int gofs = s * 64;                   // 16 floats per stage
        #pragma unroll
        for (int i = 0; i < 4; i++)
            cp_async16(dstb[i] + slot, srcb[i] + gofs);
        cp_commit();
    };

    // Prologue: start this warp's stages 0..2 before W staging.
    issue_stage(0);
    issue_stage(1);
    issue_stage(2);

    // Stage W (4224 uint4 = 33 per thread, exact) + thresholds.
    {
        uint4* d4 = reinterpret_cast<uint4*>(smem + SM_W);
        #pragma unroll
        for (int i = 0; i < 33; i++)
            d4[tid + i * 128] = g_w_pad4[tid + i * 128];
        if (tid < RULES) sThr[tid] = g_thr[tid];
    }
    __syncthreads();   // once: W visible to all warps

    float acc[2][16][4];
    #pragma unroll
    for (int t = 0; t < 2; t++)
        #pragma unroll
        for (int nt = 0; nt < 16; nt++)
            #pragma unroll
            for (int i = 0; i < 4; i++) acc[t][nt][i] = 0.0f;

    // Mainloop: 16 K-steps. Per iter (warp-local): wait stage ks, syncwarp
    // (visibility of sibling lanes' cp.async data + licenses overwrite of
    // slot (ks+3)&3 whose last reads were compute(ks-1)), issue ks+3, compute.
    #pragma unroll
    for (int ks = 0; ks < 16; ks++) {
        cp_wait_dyn(ks <= 13 ? 2 : 15 - ks);
        __syncwarp();
        if (ks < 13) issue_stage(ks + 3);

        // A fragments: rows g + 8t, k = {2q,2q+1} and {2q+8,2q+9}.
        const char* sa = smem + SM_A + warp * WSLAB
                       + (ks & (NSTAGE - 1)) * (32 * STG_ROW);
        uint32_t A[2][4];
        #pragma unroll
        for (int t = 0; t < 4; t++) {
            const char* rp = sa + (g + 8 * t) * STG_ROW + q * 8;
            float2 v0 = *reinterpret_cast<const float2*>(rp);
            float2 v1 = *reinterpret_cast<const float2*>(rp + 32);
            A[t >> 1][t & 1]       = f2_to_bf2(v0);
            A[t >> 1][2 + (t & 1)] = f2_to_bf2(v1);
        }

        const int c0 = ks * 16;
        #pragma unroll
        for (int nt = 0; nt < 16; nt++) {
            const uint32_t* bp = reinterpret_cast<const uint32_t*>(
                sW + (nt * 8 + g) * WPAD + c0 + q * 2);
            uint32_t b0 = bp[0];   // k = c0+q*2, +1
            uint32_t b1 = bp[4];   // k = c0+q*2+8, +9
            mma_bf16(acc[0][nt], A[0], b0, b1);
            mma_bf16(acc[1][nt], A[1], b0, b1);
        }
    }

    // Epilogue: threshold-count, quad reduce, coalesced store.
    const float bor = __ldg(b_or);
    #pragma unroll
    for (int t = 0; t < 2; t++) {              // A-tile rows: g+16t, g+16t+8
        float c0s = 0.0f, c1s = 0.0f;
        #pragma unroll
        for (int nt = 0; nt < 16; nt++) {
            float t0 = sThr[nt * 8 + q * 2];
            float t1 = sThr[nt * 8 + q * 2 + 1];
            c0s += (acc[t][nt][0] > t0) ? 1.0f : 0.0f;
            c0s += (acc[t][nt][1] > t1) ? 1.0f : 0.0f;
            c1s += (acc[t][nt][2] > t0) ? 1.0f : 0.0f;
            c1s += (acc[t][nt][3] > t1) ? 1.0f : 0.0f;
        }
        c0s += __shfl_xor_sync(0xFFFFFFFFu, c0s, 1);
        c0s += __shfl_xor_sync(0xFFFFFFFFu, c0s, 2);
        c1s += __shfl_xor_sync(0xFFFFFFFFu, c1s, 1);
        c1s += __shfl_xor_sync(0xFFFFFFFFu, c1s, 2);
        if (q == 0) {
            int r0 = rowbase + g + t * 16;
            int r1 = r0 + 8;
            if (r0 < nrows) out[r0] = c0s + bor;
            if (r1 < nrows) out[r1] = c1s + bor;
        }
    }
}

// ---------------------------------------------------------------------------
// kernel_launch
// ---------------------------------------------------------------------------
extern "C" void kernel_launch(void* const* d_in, const int* in_sizes, int n_in,
                              void* d_out, int out_size) {
    const float* x        = (const float*)d_in[0];
    const float* w_cancel = (const float*)d_in[1];
    const float* w_and    = (const float*)d_in[2];
    const float* b_and    = (const float*)d_in[3];
    const float* w_or     = (const float*)d_in[4];
    const float* b_or     = (const float*)d_in[5];
    float* out = (float*)d_out;

    int nrows = in_sizes[0] / FEAT;
    int nblocks = (nrows + 127) / 128;

    r2n_prep<<<RULES / 4, 128>>>(w_cancel, w_and, b_and, w_or);

    cudaFuncSetAttribute(r2n_main,
                         cudaFuncAttributeMaxDynamicSharedMemorySize, SMEM_TOTAL);
    r2n_main<<<nblocks, 128, SMEM_TOTAL>>>(x, b_or, out, nrows);

    (void)n_in; (void)out_size;
}

// round 17
// speedup vs baseline: 1.6947x; 1.1159x over previous
#include <cuda_runtime.h>
#include <cuda_bf16.h>
#include <cstdint>

// ============================================================================
// R2Ntab: out[b] = sum_r [ x[b,:]·rw[r,:] > thr[r] ] * orw[r] + b_or[0]
//   rw[r,j]  = (w_cancel[j] >= 0) ? w_and[r,j] : 0           (bf16)
//   thr[r]   = orw[r] ? 0.999999 - b_and[r] + sum relu(rw)   else +INF
// GEMM [131072 x 256] x [256 x 128] via mma.sync m16n8k16 bf16 (plain sm_103).
// R15: PERSISTENT kernel (148 CTAs x 256 thr, 1 CTA/SM), per-warp cp.async
// rings deepened to 8 stages (wait<=6, ~14KB in flight/warp), W staged once
// per SM, and W stored fragment-ordered so each B fragment is ONE conflict-
// free LDS.64. R14 showed dur == x_bytes/achieved_BW with DRAM at 48% —
// in-flight depth and L2 re-staging were the caps.
// ============================================================================

#define FEAT   256
#define RULES  128
#define WF_BYTES 65536                 // fragment-ordered W image
#define NSTAGE   8
#define STG_ROW  80                    // 16 fp32 used per row, 16B-aligned
#define STG_BYTES (32 * STG_ROW)       // 2560 per stage per warp
#define WSLAB    (NSTAGE * STG_BYTES)  // 20480 per warp
#define SM_THR   0
#define SM_WF    512
#define SM_RING  (SM_WF + WF_BYTES)    // 66048
#define SMEM_TOTAL (SM_RING + 8 * WSLAB)   // 229888
#define NCTA     148

__device__ uint4 g_w_frag4[WF_BYTES / 16];
__device__ float g_thr[RULES];

// ---------------------------------------------------------------------------
// Prep: one warp per rule. Mask by w_cancel sign, fold orw into threshold.
// Writes W in FRAGMENT ORDER: for (ks,nt), a 256B block; lane (g,q) owns 8B:
//   [W[nt*8+g][ks*16+2q], +1, W[..][ks*16+2q+8], +9]
// ---------------------------------------------------------------------------
__global__ void r2n_prep(const float* __restrict__ w_cancel,
                         const float* __restrict__ w_and,
                         const float* __restrict__ b_and,
                         const float* __restrict__ w_or) {
    int wid = threadIdx.x >> 5, lid = threadIdx.x & 31;
    int r = blockIdx.x * 4 + wid;
    int nt = r >> 3, g = r & 7;
    __nv_bfloat16* img = reinterpret_cast<__nv_bfloat16*>(g_w_frag4);

    float relu_sum = 0.0f;
    #pragma unroll
    for (int jj = 0; jj < FEAT / 32; jj++) {
        int j = lid + jj * 32;
        float wv = (w_cancel[j] >= 0.0f) ? w_and[r * FEAT + j] : 0.0f;
        relu_sum += fmaxf(wv, 0.0f);
        int ks = j >> 4, jin = j & 15;
        int half = jin >> 3, q = (jin & 7) >> 1, par = jin & 1;
        uint32_t boff = (uint32_t)(((ks * 16 + nt) * 32 + g * 4 + q) * 8
                                   + half * 4 + par * 2);
        img[boff >> 1] = __float2bfloat16(wv);
    }
    #pragma unroll
    for (int d = 16; d > 0; d >>= 1)
        relu_sum += __shfl_xor_sync(0xFFFFFFFFu, relu_sum, d);
    if (lid == 0) {
        g_thr[r] = (w_or[r] > 0.0f)
                 ? (0.999999f - b_and[r] + relu_sum)
                 : __int_as_float(0x7f800000);   // +INF: rule never fires
    }
}

// ---------------------------------------------------------------------------
// PTX helpers
// ---------------------------------------------------------------------------
__device__ __forceinline__ void mma_bf16(float* d, const uint32_t* a,
                                         uint32_t b0, uint32_t b1) {
    asm volatile(
        "mma.sync.aligned.m16n8k16.row.col.f32.bf16.bf16.f32 "
        "{%0,%1,%2,%3}, {%4,%5,%6,%7}, {%8,%9}, {%0,%1,%2,%3};"
        : "+f"(d[0]), "+f"(d[1]), "+f"(d[2]), "+f"(d[3])
        : "r"(a[0]), "r"(a[1]), "r"(a[2]), "r"(a[3]), "r"(b0), "r"(b1));
}

__device__ __forceinline__ uint32_t f2_to_bf2(float2 v) {
    __nv_bfloat162 h = __float22bfloat162_rn(v);
    return *reinterpret_cast<uint32_t*>(&h);
}

__device__ __forceinline__ uint32_t smem_u32(const void* p) {
    uint32_t a;
    asm("{ .reg .u64 t; cvta.to.shared.u64 t, %1; cvt.u32.u64 %0, t; }"
        : "=r"(a) : "l"(p));
    return a;
}

__device__ __forceinline__ void cp_async16(uint32_t dst, const void* src) {
    asm volatile("cp.async.cg.shared.global [%0], [%1], 16;"
                 :: "r"(dst), "l"(src) : "memory");
}
__device__ __forceinline__ void cp_commit() {
    asm volatile("cp.async.commit_group;" ::: "memory");
}
__device__ __forceinline__ void cp_wait(int n) {   // n folds to a constant
    if (n >= 6)      asm volatile("cp.async.wait_group 6;" ::: "memory");
    else if (n == 5) asm volatile("cp.async.wait_group 5;" ::: "memory");
    else if (n == 4) asm volatile("cp.async.wait_group 4;" ::: "memory");
    else if (n == 3) asm volatile("cp.async.wait_group 3;" ::: "memory");
    else if (n == 2) asm volatile("cp.async.wait_group 2;" ::: "memory");
    else if (n == 1) asm volatile("cp.async.wait_group 1;" ::: "memory");
    else             asm volatile("cp.async.wait_group 0;" ::: "memory");
}

// ---------------------------------------------------------------------------
// Main (persistent): 256 threads = 8 warps/CTA, 148 CTAs. Each warp owns a
// stream of 32-row chunks (stride 148*8). Private depth-8 cp.async ring per
// warp; issue-ahead 7, wait<=6. No CTA barrier after W staging.
// ---------------------------------------------------------------------------
__global__ void __launch_bounds__(256, 1)
r2n_main(const float* __restrict__ x,
         const float* __restrict__ b_or,
         float* __restrict__ out,
         int nrows, int nchunks) {
    extern __shared__ char smem[];
    float* sThr = reinterpret_cast<float*>(smem + SM_THR);
    const uint32_t sb = smem_u32(smem);
    const int tid = threadIdx.x;
    const int lane = tid & 31, warp = tid >> 5;
    const int l8 = lane >> 2, lq = lane & 3;       // g, q aliases
    const int g = l8, q = lq;
    const int wg = blockIdx.x * 8 + warp;          // global warp id
    const int NW = NCTA * 8;                       // 1184

    // Ring dst base (slot- and i-invariant part).
    const uint32_t dstbase = sb + SM_RING + (uint32_t)(warp * WSLAB)
                           + (uint32_t)(l8 * STG_ROW + lq * 16);

    // Per-chunk src pointers: row c*32 + l8 + 8i, byte col lq*16.
    const char* srcC[4];
    #define FILL_SRC(sv, c)                                                    \
        do {                                                                   \
            _Pragma("unroll")                                                  \
            for (int i = 0; i < 4; i++) {                                      \
                long rg = (long)(c) * 32 + l8 + 8 * i;                         \
                if (rg >= nrows) rg = nrows - 1;                               \
                (sv)[i] = reinterpret_cast<const char*>(x)                     \
                        + (size_t)rg * (FEAT * 4) + lq * 16;                   \
            }                                                                  \
        } while (0)

    // issue stage s (0..15 within chunk 'sv'), ring slot 'slot'.
    #define ISSUE(sv, s, slot)                                                 \
        do {                                                                   \
            const uint32_t _d = dstbase + (uint32_t)((slot) * STG_BYTES);      \
            _Pragma("unroll")                                                  \
            for (int i = 0; i < 4; i++)                                        \
                cp_async16(_d + i * (8 * STG_ROW), (sv)[i] + (s) * 64);        \
            cp_commit();                                                       \
        } while (0)

    // Prologue: issue stages 0..6 of this warp's first chunk before W staging.
    if (wg < nchunks) {
        FILL_SRC(srcC, wg);
        #pragma unroll
        for (int s = 0; s < 7; s++) ISSUE(srcC, s, s);
    }

    // Stage W (4096 uint4, 16 per thread exact) + thresholds. Once per SM.
    {
        uint4* d4 = reinterpret_cast<uint4*>(smem + SM_WF);
        #pragma unroll
        for (int i = 0; i < 16; i++)
            d4[tid + i * 256] = g_w_frag4[tid + i * 256];
        if (tid < RULES) sThr[tid] = g_thr[tid];
    }
    __syncthreads();
    const float bor = __ldg(b_or);

    for (int c = wg; c < nchunks; c += NW) {
        const int cn = c + NW;
        const bool hasNext = cn < nchunks;
        const char* srcN[4];
        if (hasNext) FILL_SRC(srcN, cn);

        float acc[2][16][4];
        #pragma unroll
        for (int t = 0; t < 2; t++)
            #pragma unroll
            for (int nt = 0; nt < 16; nt++)
                #pragma unroll
                for (int i = 0; i < 4; i++) acc[t][nt][i] = 0.0f;

        // 16 K-steps. compute slot = ks&7; issue global stage ks+7 into slot
        // (ks+7)&7 = (ks-1)&7, whose last reads were compute(ks-1) (done).
        #pragma unroll
        for (int ks = 0; ks < 16; ks++) {
            if (hasNext) cp_wait(6);
            else         cp_wait(15 - ks < 6 ? 15 - ks : 6);
            __syncwarp();
            if (ks <= 8)       ISSUE(srcC, ks + 7, (ks + 7) & 7);
            else if (hasNext)  ISSUE(srcN, ks - 9, (ks + 7) & 7);

            // A fragments from ring slot ks&7: rows g+8t, k {2q,2q+1},{+8,+9}.
            const char* sa = smem + SM_RING + warp * WSLAB
                           + (ks & 7) * STG_BYTES;
            uint32_t A[2][4];
            #pragma unroll
            for (int t = 0; t < 4; t++) {
                const char* rp = sa + (g + 8 * t) * STG_ROW + q * 8;
                float2 v0 = *reinterpret_cast<const float2*>(rp);
                float2 v1 = *reinterpret_cast<const float2*>(rp + 32);
                A[t >> 1][t & 1]       = f2_to_bf2(v0);
                A[t >> 1][2 + (t & 1)] = f2_to_bf2(v1);
            }

            // B fragments: one conflict-free LDS.64 per nt (fragment order).
            const char* wf = smem + SM_WF + (size_t)ks * (16 * 256) + lane * 8;
            #pragma unroll
            for (int nt = 0; nt < 16; nt++) {
                uint2 b = *reinterpret_cast<const uint2*>(wf + nt * 256);
                mma_bf16(acc[0][nt], A[0], b.x, b.y);
                mma_bf16(acc[1][nt], A[1], b.x, b.y);
            }
        }

        // Epilogue: threshold-count, quad reduce, store rows c*32 + {g,g+8,...}.
        const int rowbase = c * 32;
        #pragma unroll
        for (int t = 0; t < 2; t++) {
            float c0s = 0.0f, c1s = 0.0f;
            #pragma unroll
            for (int nt = 0; nt < 16; nt++) {
                float t0 = sThr[nt * 8 + q * 2];
                float t1 = sThr[nt * 8 + q * 2 + 1];
                c0s += (acc[t][nt][0] > t0) ? 1.0f : 0.0f;
                c0s += (acc[t][nt][1] > t1) ? 1.0f : 0.0f;
                c1s += (acc[t][nt][2] > t0) ? 1.0f : 0.0f;
                c1s += (acc[t][nt][3] > t1) ? 1.0f : 0.0f;
            }
            c0s += __shfl_xor_sync(0xFFFFFFFFu, c0s, 1);
            c0s += __shfl_xor_sync(0xFFFFFFFFu, c0s, 2);
            c1s += __shfl_xor_sync(0xFFFFFFFFu, c1s, 1);
            c1s += __shfl_xor_sync(0xFFFFFFFFu, c1s, 2);
            if (q == 0) {
                int r0 = rowbase + g + t * 16;
                int r1 = r0 + 8;
                if (r0 < nrows) out[r0] = c0s + bor;
                if (r1 < nrows) out[r1] = c1s + bor;
            }
        }

        #pragma unroll
        for (int i = 0; i < 4; i++) srcC[i] = srcN[i];
    }
    #undef ISSUE
    #undef FILL_SRC
}

// ---------------------------------------------------------------------------
// kernel_launch
// ---------------------------------------------------------------------------
extern "C" void kernel_launch(void* const* d_in, const int* in_sizes, int n_in,
                              void* d_out, int out_size) {
    const float* x        = (const float*)d_in[0];
    const float* w_cancel = (const float*)d_in[1];
    const float* w_and    = (const float*)d_in[2];
    const float* b_and    = (const float*)d_in[3];
    const float* w_or     = (const float*)d_in[4];
    const float* b_or     = (const float*)d_in[5];
    float* out = (float*)d_out;

    int nrows = in_sizes[0] / FEAT;
    int nchunks = (nrows + 31) / 32;

    r2n_prep<<<RULES / 4, 128>>>(w_cancel, w_and, b_and, w_or);

    cudaFuncSetAttribute(r2n_main,
                         cudaFuncAttributeMaxDynamicSharedMemorySize, SMEM_TOTAL);
    r2n_main<<<NCTA, 256, SMEM_TOTAL>>>(x, b_or, out, nrows, nchunks);

    (void)n_in; (void)out_size;
}